// round 3
// baseline (speedup 1.0000x reference)
#include <cuda_runtime.h>

#define N_NODES 50000
#define N_EDGES 800000
#define F 64
#define NCLS 10

// Scratch (__device__ globals: allocation-free rule). Accessed DIRECTLY by
// kernels as symbols — no cudaGetSymbolAddress anywhere.
__device__ float g_h[N_NODES * F];
__device__ float g_x[N_NODES * F];
__device__ int   g_deg[N_NODES];
__device__ int   g_offs[N_NODES + 1];
__device__ int   g_cursor[N_NODES];
__device__ int   g_csr[N_EDGES];
__device__ int   g_is64;

// ---------------------------------------------------------------------------
// Detect edge-index dtype: if int64, ids < 50000 => every odd 32-bit word == 0
// ---------------------------------------------------------------------------
__global__ void detect_kernel(const int* __restrict__ edges_raw) {
    __shared__ int any_nonzero;
    if (threadIdx.x == 0) any_nonzero = 0;
    __syncthreads();
    int nz = 0;
    for (int i = threadIdx.x; i < 2048; i += blockDim.x)
        if (edges_raw[2 * i + 1] != 0) nz = 1;
    if (nz) any_nonzero = 1;
    __syncthreads();
    if (threadIdx.x == 0) g_is64 = (any_nonzero == 0) ? 1 : 0;
}

__device__ __forceinline__ int load_id(const int* __restrict__ raw, int is64, int idx) {
    return is64 ? raw[2 * idx] : raw[idx];
}

// ---------------------------------------------------------------------------
// CSR build
// ---------------------------------------------------------------------------
__global__ void zero_deg_kernel() {
    int i = blockIdx.x * blockDim.x + threadIdx.x;
    if (i < N_NODES) g_deg[i] = 0;
}

__global__ void hist_kernel(const int* __restrict__ edges_raw) {
    int e = blockIdx.x * blockDim.x + threadIdx.x;
    if (e < N_EDGES) {
        int d = load_id(edges_raw, g_is64, N_EDGES + e);  // dst row
        atomicAdd(&g_deg[d], 1);
    }
}

__global__ void prefix_kernel() {
    __shared__ int buf[1024];
    __shared__ int running;
    int tid = threadIdx.x;
    if (tid == 0) running = 0;
    __syncthreads();
    for (int base = 0; base < N_NODES; base += 1024) {
        int i = base + tid;
        int v = (i < N_NODES) ? g_deg[i] : 0;
        buf[tid] = v;
        __syncthreads();
#pragma unroll
        for (int off = 1; off < 1024; off <<= 1) {
            int add = (tid >= off) ? buf[tid - off] : 0;
            __syncthreads();
            buf[tid] += add;
            __syncthreads();
        }
        int excl = running + buf[tid] - v;
        if (i < N_NODES) { g_offs[i] = excl; g_cursor[i] = excl; }
        __syncthreads();
        if (tid == 1023) running += buf[1023];
        __syncthreads();
    }
    if (tid == 0) g_offs[N_NODES] = running;
}

__global__ void csr_scatter_kernel(const int* __restrict__ edges_raw) {
    int e = blockIdx.x * blockDim.x + threadIdx.x;
    if (e >= N_EDGES) return;
    int is64 = g_is64;
    int s = load_id(edges_raw, is64, e);
    int d = load_id(edges_raw, is64, N_EDGES + e);
    int pos = atomicAdd(&g_cursor[d], 1);
    g_csr[pos] = s;
}

// ---------------------------------------------------------------------------
// Aggregation (gather): g_h[n] = x[n] + sum_{s in N_in(n)} x[s]
// 16 threads per node, float4 per thread.
// ---------------------------------------------------------------------------
__global__ void agg_kernel(const float* __restrict__ feat, int first) {
    const float* __restrict__ x = first ? feat : (const float*)g_x;
    int tid  = threadIdx.x;
    int node = blockIdx.x * 16 + (tid >> 4);
    int t    = tid & 15;
    if (node >= N_NODES) return;

    float4 acc = *(const float4*)(x + (size_t)node * F + t * 4);
    int jb = g_offs[node];
    int je = g_offs[node + 1];
    for (int j = jb; j < je; j++) {
        int s = g_csr[j];
        float4 v = *(const float4*)(x + (size_t)s * F + t * 4);
        acc.x += v.x; acc.y += v.y; acc.z += v.z; acc.w += v.w;
    }
    *(float4*)(g_h + (size_t)node * F + t * 4) = acc;
}

// ---------------------------------------------------------------------------
// g_x = relu( relu(g_h @ W1 + b1) @ W2 + b2 )
// 64-row tile per block, 256 threads as 16x16, 4x4 register microtile.
// ---------------------------------------------------------------------------
__global__ void mlp_kernel(const float* __restrict__ W1, const float* __restrict__ b1,
                           const float* __restrict__ W2, const float* __restrict__ b2) {
    __shared__ float Hs[64][65];
    __shared__ float Ws[64][64];
    __shared__ float bias[64];

    int tid = threadIdx.x;
    int tx = tid & 15;
    int ty = tid >> 4;
    int row0 = blockIdx.x * 64;

    for (int i = tid; i < 64 * 16; i += 256) {
        int r = i >> 4;
        int c = (i & 15) << 2;
        float4 v = make_float4(0.f, 0.f, 0.f, 0.f);
        if (row0 + r < N_NODES) v = *(const float4*)(g_h + (size_t)(row0 + r) * F + c);
        Hs[r][c] = v.x; Hs[r][c + 1] = v.y; Hs[r][c + 2] = v.z; Hs[r][c + 3] = v.w;
    }
    for (int i = tid; i < 1024; i += 256)
        ((float4*)&Ws[0][0])[i] = ((const float4*)W1)[i];
    if (tid < 64) bias[tid] = b1[tid];
    __syncthreads();

    float acc[4][4];
#pragma unroll
    for (int i = 0; i < 4; i++)
#pragma unroll
        for (int j = 0; j < 4; j++) acc[i][j] = bias[tx * 4 + j];

#pragma unroll 8
    for (int k = 0; k < 64; k++) {
        float a0 = Hs[ty * 4 + 0][k];
        float a1 = Hs[ty * 4 + 1][k];
        float a2 = Hs[ty * 4 + 2][k];
        float a3 = Hs[ty * 4 + 3][k];
        float4 b = *(float4*)&Ws[k][tx * 4];
        acc[0][0] += a0 * b.x; acc[0][1] += a0 * b.y; acc[0][2] += a0 * b.z; acc[0][3] += a0 * b.w;
        acc[1][0] += a1 * b.x; acc[1][1] += a1 * b.y; acc[1][2] += a1 * b.z; acc[1][3] += a1 * b.w;
        acc[2][0] += a2 * b.x; acc[2][1] += a2 * b.y; acc[2][2] += a2 * b.z; acc[2][3] += a2 * b.w;
        acc[3][0] += a3 * b.x; acc[3][1] += a3 * b.y; acc[3][2] += a3 * b.z; acc[3][3] += a3 * b.w;
    }
    __syncthreads();

#pragma unroll
    for (int i = 0; i < 4; i++)
#pragma unroll
        for (int j = 0; j < 4; j++)
            Hs[ty * 4 + i][tx * 4 + j] = fmaxf(acc[i][j], 0.f);
    for (int i = tid; i < 1024; i += 256)
        ((float4*)&Ws[0][0])[i] = ((const float4*)W2)[i];
    if (tid < 64) bias[tid] = b2[tid];
    __syncthreads();

#pragma unroll
    for (int i = 0; i < 4; i++)
#pragma unroll
        for (int j = 0; j < 4; j++) acc[i][j] = bias[tx * 4 + j];

#pragma unroll 8
    for (int k = 0; k < 64; k++) {
        float a0 = Hs[ty * 4 + 0][k];
        float a1 = Hs[ty * 4 + 1][k];
        float a2 = Hs[ty * 4 + 2][k];
        float a3 = Hs[ty * 4 + 3][k];
        float4 b = *(float4*)&Ws[k][tx * 4];
        acc[0][0] += a0 * b.x; acc[0][1] += a0 * b.y; acc[0][2] += a0 * b.z; acc[0][3] += a0 * b.w;
        acc[1][0] += a1 * b.x; acc[1][1] += a1 * b.y; acc[1][2] += a1 * b.z; acc[1][3] += a1 * b.w;
        acc[2][0] += a2 * b.x; acc[2][1] += a2 * b.y; acc[2][2] += a2 * b.z; acc[2][3] += a2 * b.w;
        acc[3][0] += a3 * b.x; acc[3][1] += a3 * b.y; acc[3][2] += a3 * b.z; acc[3][3] += a3 * b.w;
    }

#pragma unroll
    for (int i = 0; i < 4; i++) {
        int r = row0 + ty * 4 + i;
        if (r < N_NODES) {
            float4 o;
            o.x = fmaxf(acc[i][0], 0.f); o.y = fmaxf(acc[i][1], 0.f);
            o.z = fmaxf(acc[i][2], 0.f); o.w = fmaxf(acc[i][3], 0.f);
            *(float4*)(g_x + (size_t)r * F + tx * 4) = o;
        }
    }
}

// ---------------------------------------------------------------------------
// out = g_x @ W_lin + b_lin   (64 -> 10), 128 rows/block, 1 thread per row
// ---------------------------------------------------------------------------
__global__ void lin_kernel(const float* __restrict__ W, const float* __restrict__ b,
                           float* __restrict__ out) {
    __shared__ float Xs[128][65];
    __shared__ float Ws[64 * NCLS];
    __shared__ float bs[NCLS];

    int tid = threadIdx.x;
    int row0 = blockIdx.x * 128;

    for (int i = tid; i < 128 * 16; i += 128) {
        int r = i >> 4;
        int c = (i & 15) << 2;
        float4 v = make_float4(0.f, 0.f, 0.f, 0.f);
        if (row0 + r < N_NODES) v = *(const float4*)(g_x + (size_t)(row0 + r) * F + c);
        Xs[r][c] = v.x; Xs[r][c + 1] = v.y; Xs[r][c + 2] = v.z; Xs[r][c + 3] = v.w;
    }
    for (int i = tid; i < 64 * NCLS; i += 128) Ws[i] = W[i];
    if (tid < NCLS) bs[tid] = b[tid];
    __syncthreads();

    int row = row0 + tid;
    float acc[NCLS];
#pragma unroll
    for (int c = 0; c < NCLS; c++) acc[c] = bs[c];
#pragma unroll 8
    for (int k = 0; k < 64; k++) {
        float xv = Xs[tid][k];
#pragma unroll
        for (int c = 0; c < NCLS; c++) acc[c] += xv * Ws[k * NCLS + c];
    }
    if (row < N_NODES) {
#pragma unroll
        for (int c = 0; c < NCLS; c++) out[(size_t)row * NCLS + c] = acc[c];
    }
}

// ---------------------------------------------------------------------------
// Launch: kernel launches ONLY — no other CUDA host APIs.
// ---------------------------------------------------------------------------
extern "C" void kernel_launch(void* const* d_in, const int* in_sizes, int n_in,
                              void* d_out, int out_size) {
    const float* feat      = (const float*)d_in[0];
    const int*   edges_raw = (const int*)d_in[1];

    const float* W1[3] = { (const float*)d_in[2],  (const float*)d_in[6],  (const float*)d_in[10] };
    const float* b1[3] = { (const float*)d_in[3],  (const float*)d_in[7],  (const float*)d_in[11] };
    const float* W2[3] = { (const float*)d_in[4],  (const float*)d_in[8],  (const float*)d_in[12] };
    const float* b2[3] = { (const float*)d_in[5],  (const float*)d_in[9],  (const float*)d_in[13] };
    const float* Wl = (const float*)d_in[14];
    const float* bl = (const float*)d_in[15];
    float* out = (float*)d_out;

    dim3 node_grid((N_NODES + 255) / 256);
    dim3 edge_grid((N_EDGES + 255) / 256);
    dim3 agg_grid((N_NODES + 15) / 16);
    dim3 mlp_grid((N_NODES + 63) / 64);
    dim3 lin_grid((N_NODES + 127) / 128);

    detect_kernel<<<1, 256>>>(edges_raw);
    zero_deg_kernel<<<node_grid, 256>>>();
    hist_kernel<<<edge_grid, 256>>>(edges_raw);
    prefix_kernel<<<1, 1024>>>();
    csr_scatter_kernel<<<edge_grid, 256>>>(edges_raw);

    for (int l = 0; l < 3; l++) {
        agg_kernel<<<agg_grid, 256>>>(feat, l == 0 ? 1 : 0);
        mlp_kernel<<<mlp_grid, 256>>>(W1[l], b1[l], W2[l], b2[l]);
    }
    lin_kernel<<<lin_grid, 128>>>(Wl, bl, out);
}

// round 4
// speedup vs baseline: 1.3922x; 1.3922x over previous
#include <cuda_runtime.h>

#define N_NODES 50000
#define N_EDGES 800000
#define F 64
#define NCLS 10

#define SCAN_CHUNK 512
#define SCAN_BLOCKS ((N_NODES + SCAN_CHUNK - 1) / SCAN_CHUNK)   // 98

// Scratch (__device__ globals: allocation-free rule). Accessed directly as
// symbols — no cudaGetSymbolAddress (it breaks graph capture on this harness).
__device__ float g_h[N_NODES * F];
__device__ float g_x[N_NODES * F];
__device__ int   g_deg[N_NODES];
__device__ int   g_offs[N_NODES + 1];
__device__ int   g_cursor[N_NODES];
__device__ int   g_csr[N_EDGES];
__device__ int   g_blocksum[SCAN_BLOCKS];
__device__ int   g_is64;

// ---------------------------------------------------------------------------
// Detect edge-index dtype: int64 with ids < 50000 => every odd 32-bit word == 0
// ---------------------------------------------------------------------------
__global__ void detect_kernel(const int* __restrict__ edges_raw) {
    __shared__ int any_nonzero;
    if (threadIdx.x == 0) any_nonzero = 0;
    __syncthreads();
    int nz = 0;
    for (int i = threadIdx.x; i < 2048; i += blockDim.x)
        if (edges_raw[2 * i + 1] != 0) nz = 1;
    if (nz) any_nonzero = 1;
    __syncthreads();
    if (threadIdx.x == 0) g_is64 = (any_nonzero == 0) ? 1 : 0;
}

__device__ __forceinline__ int load_id(const int* __restrict__ raw, int is64, int idx) {
    return is64 ? raw[2 * idx] : raw[idx];
}

// ---------------------------------------------------------------------------
// CSR build
// ---------------------------------------------------------------------------
__global__ void zero_deg_kernel() {
    int i = blockIdx.x * blockDim.x + threadIdx.x;
    if (i < N_NODES) g_deg[i] = 0;
}

__global__ void hist_kernel(const int* __restrict__ edges_raw) {
    int e = blockIdx.x * blockDim.x + threadIdx.x;
    if (e < N_EDGES) {
        int d = load_id(edges_raw, g_is64, N_EDGES + e);
        atomicAdd(&g_deg[d], 1);
    }
}

// Scan step 1: per-block (512-wide) exclusive scan via warp shuffles.
// Writes local-exclusive prefix into g_offs, block total into g_blocksum.
__global__ void scan_local_kernel() {
    __shared__ int warp_sums[SCAN_CHUNK / 32];
    int tid  = threadIdx.x;
    int gid  = blockIdx.x * SCAN_CHUNK + tid;
    int lane = tid & 31;
    int wid  = tid >> 5;

    int v = (gid < N_NODES) ? g_deg[gid] : 0;
    int x = v;
#pragma unroll
    for (int off = 1; off < 32; off <<= 1) {
        int y = __shfl_up_sync(0xFFFFFFFFu, x, off);
        if (lane >= off) x += y;
    }
    if (lane == 31) warp_sums[wid] = x;
    __syncthreads();
    if (wid == 0) {
        int s = (lane < SCAN_CHUNK / 32) ? warp_sums[lane] : 0;
#pragma unroll
        for (int off = 1; off < SCAN_CHUNK / 32; off <<= 1) {
            int y = __shfl_up_sync(0xFFFFFFFFu, s, off);
            if (lane >= off) s += y;
        }
        if (lane < SCAN_CHUNK / 32) warp_sums[lane] = s;
    }
    __syncthreads();
    int base = (wid > 0) ? warp_sums[wid - 1] : 0;
    int incl = base + x;
    if (gid < N_NODES) g_offs[gid] = incl - v;          // local exclusive
    if (tid == SCAN_CHUNK - 1) g_blocksum[blockIdx.x] = incl;
}

// Scan step 2: exclusive scan of the 98 block sums (single block, 128 thr).
__global__ void scan_spine_kernel() {
    __shared__ int ws[4];
    int tid  = threadIdx.x;             // 128 threads
    int lane = tid & 31;
    int wid  = tid >> 5;
    int v = (tid < SCAN_BLOCKS) ? g_blocksum[tid] : 0;
    int x = v;
#pragma unroll
    for (int off = 1; off < 32; off <<= 1) {
        int y = __shfl_up_sync(0xFFFFFFFFu, x, off);
        if (lane >= off) x += y;
    }
    if (lane == 31) ws[wid] = x;
    __syncthreads();
    if (tid == 0) {
        int r = 0;
#pragma unroll
        for (int i = 0; i < 4; i++) { int t = ws[i]; ws[i] = r; r += t; }
    }
    __syncthreads();
    int excl = ws[wid] + x - v;
    if (tid < SCAN_BLOCKS) g_blocksum[tid] = excl;
    if (tid == SCAN_BLOCKS - 1) g_offs[N_NODES] = excl + v;
}

// Scan step 3: add spine offset; materialize offs + cursor.
__global__ void scan_add_kernel() {
    int gid = blockIdx.x * SCAN_CHUNK + threadIdx.x;
    if (gid < N_NODES) {
        int o = g_offs[gid] + g_blocksum[blockIdx.x];
        g_offs[gid]   = o;
        g_cursor[gid] = o;
    }
}

__global__ void csr_scatter_kernel(const int* __restrict__ edges_raw) {
    int e = blockIdx.x * blockDim.x + threadIdx.x;
    if (e >= N_EDGES) return;
    int is64 = g_is64;
    int s = load_id(edges_raw, is64, e);
    int d = load_id(edges_raw, is64, N_EDGES + e);
    int pos = atomicAdd(&g_cursor[d], 1);
    g_csr[pos] = s;
}

// ---------------------------------------------------------------------------
// Aggregation (gather): g_h[n] = x[n] + sum_{s in N_in(n)} x[s]
// 16 threads per node, float4 per thread.
// ---------------------------------------------------------------------------
__global__ void agg_kernel(const float* __restrict__ feat, int first) {
    const float* __restrict__ x = first ? feat : (const float*)g_x;
    int tid  = threadIdx.x;
    int node = blockIdx.x * 16 + (tid >> 4);
    int t    = tid & 15;
    if (node >= N_NODES) return;

    float4 acc = *(const float4*)(x + (size_t)node * F + t * 4);
    int jb = g_offs[node];
    int je = g_offs[node + 1];
    for (int j = jb; j < je; j++) {
        int s = g_csr[j];
        float4 v = *(const float4*)(x + (size_t)s * F + t * 4);
        acc.x += v.x; acc.y += v.y; acc.z += v.z; acc.w += v.w;
    }
    *(float4*)(g_h + (size_t)node * F + t * 4) = acc;
}

// ---------------------------------------------------------------------------
// g_x = relu( relu(g_h @ W1 + b1) @ W2 + b2 )
// 64-row tile per block, 256 threads as 16x16, 4x4 register microtile.
// ---------------------------------------------------------------------------
__global__ void mlp_kernel(const float* __restrict__ W1, const float* __restrict__ b1,
                           const float* __restrict__ W2, const float* __restrict__ b2) {
    __shared__ float Hs[64][65];
    __shared__ float Ws[64][64];
    __shared__ float bias[64];

    int tid = threadIdx.x;
    int tx = tid & 15;
    int ty = tid >> 4;
    int row0 = blockIdx.x * 64;

    for (int i = tid; i < 64 * 16; i += 256) {
        int r = i >> 4;
        int c = (i & 15) << 2;
        float4 v = make_float4(0.f, 0.f, 0.f, 0.f);
        if (row0 + r < N_NODES) v = *(const float4*)(g_h + (size_t)(row0 + r) * F + c);
        Hs[r][c] = v.x; Hs[r][c + 1] = v.y; Hs[r][c + 2] = v.z; Hs[r][c + 3] = v.w;
    }
    for (int i = tid; i < 1024; i += 256)
        ((float4*)&Ws[0][0])[i] = ((const float4*)W1)[i];
    if (tid < 64) bias[tid] = b1[tid];
    __syncthreads();

    float acc[4][4];
#pragma unroll
    for (int i = 0; i < 4; i++)
#pragma unroll
        for (int j = 0; j < 4; j++) acc[i][j] = bias[tx * 4 + j];

#pragma unroll 8
    for (int k = 0; k < 64; k++) {
        float a0 = Hs[ty * 4 + 0][k];
        float a1 = Hs[ty * 4 + 1][k];
        float a2 = Hs[ty * 4 + 2][k];
        float a3 = Hs[ty * 4 + 3][k];
        float4 b = *(float4*)&Ws[k][tx * 4];
        acc[0][0] += a0 * b.x; acc[0][1] += a0 * b.y; acc[0][2] += a0 * b.z; acc[0][3] += a0 * b.w;
        acc[1][0] += a1 * b.x; acc[1][1] += a1 * b.y; acc[1][2] += a1 * b.z; acc[1][3] += a1 * b.w;
        acc[2][0] += a2 * b.x; acc[2][1] += a2 * b.y; acc[2][2] += a2 * b.z; acc[2][3] += a2 * b.w;
        acc[3][0] += a3 * b.x; acc[3][1] += a3 * b.y; acc[3][2] += a3 * b.z; acc[3][3] += a3 * b.w;
    }
    __syncthreads();

#pragma unroll
    for (int i = 0; i < 4; i++)
#pragma unroll
        for (int j = 0; j < 4; j++)
            Hs[ty * 4 + i][tx * 4 + j] = fmaxf(acc[i][j], 0.f);
    for (int i = tid; i < 1024; i += 256)
        ((float4*)&Ws[0][0])[i] = ((const float4*)W2)[i];
    if (tid < 64) bias[tid] = b2[tid];
    __syncthreads();

#pragma unroll
    for (int i = 0; i < 4; i++)
#pragma unroll
        for (int j = 0; j < 4; j++) acc[i][j] = bias[tx * 4 + j];

#pragma unroll 8
    for (int k = 0; k < 64; k++) {
        float a0 = Hs[ty * 4 + 0][k];
        float a1 = Hs[ty * 4 + 1][k];
        float a2 = Hs[ty * 4 + 2][k];
        float a3 = Hs[ty * 4 + 3][k];
        float4 b = *(float4*)&Ws[k][tx * 4];
        acc[0][0] += a0 * b.x; acc[0][1] += a0 * b.y; acc[0][2] += a0 * b.z; acc[0][3] += a0 * b.w;
        acc[1][0] += a1 * b.x; acc[1][1] += a1 * b.y; acc[1][2] += a1 * b.z; acc[1][3] += a1 * b.w;
        acc[2][0] += a2 * b.x; acc[2][1] += a2 * b.y; acc[2][2] += a2 * b.z; acc[2][3] += a2 * b.w;
        acc[3][0] += a3 * b.x; acc[3][1] += a3 * b.y; acc[3][2] += a3 * b.z; acc[3][3] += a3 * b.w;
    }

#pragma unroll
    for (int i = 0; i < 4; i++) {
        int r = row0 + ty * 4 + i;
        if (r < N_NODES) {
            float4 o;
            o.x = fmaxf(acc[i][0], 0.f); o.y = fmaxf(acc[i][1], 0.f);
            o.z = fmaxf(acc[i][2], 0.f); o.w = fmaxf(acc[i][3], 0.f);
            *(float4*)(g_x + (size_t)r * F + tx * 4) = o;
        }
    }
}

// ---------------------------------------------------------------------------
// out = g_x @ W_lin + b_lin   (64 -> 10), 128 rows/block, 1 thread per row
// ---------------------------------------------------------------------------
__global__ void lin_kernel(const float* __restrict__ W, const float* __restrict__ b,
                           float* __restrict__ out) {
    __shared__ float Xs[128][65];
    __shared__ float Ws[64 * NCLS];
    __shared__ float bs[NCLS];

    int tid = threadIdx.x;
    int row0 = blockIdx.x * 128;

    for (int i = tid; i < 128 * 16; i += 128) {
        int r = i >> 4;
        int c = (i & 15) << 2;
        float4 v = make_float4(0.f, 0.f, 0.f, 0.f);
        if (row0 + r < N_NODES) v = *(const float4*)(g_x + (size_t)(row0 + r) * F + c);
        Xs[r][c] = v.x; Xs[r][c + 1] = v.y; Xs[r][c + 2] = v.z; Xs[r][c + 3] = v.w;
    }
    for (int i = tid; i < 64 * NCLS; i += 128) Ws[i] = W[i];
    if (tid < NCLS) bs[tid] = b[tid];
    __syncthreads();

    int row = row0 + tid;
    float acc[NCLS];
#pragma unroll
    for (int c = 0; c < NCLS; c++) acc[c] = bs[c];
#pragma unroll 8
    for (int k = 0; k < 64; k++) {
        float xv = Xs[tid][k];
#pragma unroll
        for (int c = 0; c < NCLS; c++) acc[c] += xv * Ws[k * NCLS + c];
    }
    if (row < N_NODES) {
#pragma unroll
        for (int c = 0; c < NCLS; c++) out[(size_t)row * NCLS + c] = acc[c];
    }
}

// ---------------------------------------------------------------------------
// Launch: kernel launches ONLY.
// ---------------------------------------------------------------------------
extern "C" void kernel_launch(void* const* d_in, const int* in_sizes, int n_in,
                              void* d_out, int out_size) {
    const float* feat      = (const float*)d_in[0];
    const int*   edges_raw = (const int*)d_in[1];

    const float* W1[3] = { (const float*)d_in[2],  (const float*)d_in[6],  (const float*)d_in[10] };
    const float* b1[3] = { (const float*)d_in[3],  (const float*)d_in[7],  (const float*)d_in[11] };
    const float* W2[3] = { (const float*)d_in[4],  (const float*)d_in[8],  (const float*)d_in[12] };
    const float* b2[3] = { (const float*)d_in[5],  (const float*)d_in[9],  (const float*)d_in[13] };
    const float* Wl = (const float*)d_in[14];
    const float* bl = (const float*)d_in[15];
    float* out = (float*)d_out;

    dim3 node_grid((N_NODES + 255) / 256);
    dim3 edge_grid((N_EDGES + 255) / 256);
    dim3 agg_grid((N_NODES + 15) / 16);
    dim3 mlp_grid((N_NODES + 63) / 64);
    dim3 lin_grid((N_NODES + 127) / 128);

    detect_kernel<<<1, 256>>>(edges_raw);
    zero_deg_kernel<<<node_grid, 256>>>();
    hist_kernel<<<edge_grid, 256>>>(edges_raw);
    scan_local_kernel<<<SCAN_BLOCKS, SCAN_CHUNK>>>();
    scan_spine_kernel<<<1, 128>>>();
    scan_add_kernel<<<SCAN_BLOCKS, SCAN_CHUNK>>>();
    csr_scatter_kernel<<<edge_grid, 256>>>(edges_raw);

    for (int l = 0; l < 3; l++) {
        agg_kernel<<<agg_grid, 256>>>(feat, l == 0 ? 1 : 0);
        mlp_kernel<<<mlp_grid, 256>>>(W1[l], b1[l], W2[l], b2[l]);
    }
    lin_kernel<<<lin_grid, 128>>>(Wl, bl, out);
}